// round 11
// baseline (speedup 1.0000x reference)
#include <cuda_runtime.h>

#define BH_ 16

// gmem scratch
__device__ float4 g_xs4[BH_ * 1024];          // softmaxed x, stride 32 floats
__device__ float  g_sv [BH_ * 128 * 36];      // sorted values, stride 36
__device__ float  g_qA [BH_ * 128 * 33];      // 1 - prefix1(r)     (coeff 0.5u^2)
__device__ float  g_qB [BH_ * 128 * 33];      // 0.5 * prefix2(r)   (coeff u)
__device__ float  g_qC [BH_ * 128 * 33];      // -prefix3(r)/6      (constant)

static const int SMEM_PROJ = (8 * 256 + 32 * 257 + 8 * 32) * 4;            // 42112
static const int SMEM_SPL  = (3 * 128 * 33 + 128 * 36 + 128 * 32
                              + 8 * 128 + 16 * 32) * 4;                    // 91648

__device__ __forceinline__ float wmax(float v) {
    #pragma unroll
    for (int o = 16; o > 0; o >>= 1) v = fmaxf(v, __shfl_xor_sync(0xffffffffu, v, o));
    return v;
}
__device__ __forceinline__ float wsum(float v) {
    #pragma unroll
    for (int o = 16; o > 0; o >>= 1) v += __shfl_xor_sync(0xffffffffu, v, o);
    return v;
}

// ---------------------------------------------------------------------------
// K1: in-proj GEMM + softmax + counting-rank tables + out := b_out (bias init).
// grid(32,8), 256 thr.  [unchanged from R10]
// ---------------------------------------------------------------------------
__global__ void k_proj(const float* __restrict__ inp,
                       const float* __restrict__ w_in,
                       const float* __restrict__ b_in,
                       const float* __restrict__ b_out,
                       float* __restrict__ out) {
    extern __shared__ float sm[];
    float* xs = sm;                 // [8][256]
    float* ws = sm + 8 * 256;       // [32][257]
    float* ps = ws + 32 * 257;      // [8][32]

    const int t = threadIdx.x, lane = t & 31, wid = t >> 5;
    const int r0 = blockIdx.x * 8, hd = blockIdx.y, c0 = hd * 32;

    {
        const int idx = ((blockIdx.y * 32 + blockIdx.x) << 8) + t;
        out[idx] = b_out[idx & 255];
    }

    #pragma unroll
    for (int f = t; f < 512; f += 256) {
        const int r = f >> 6, kq = f & 63;
        *(float4*)(xs + r * 256 + kq * 4) = *(const float4*)(inp + (r0 + r) * 256 + kq * 4);
    }
    #pragma unroll
    for (int rr = 0; rr < 4; ++rr) {
        const int cc = wid * 4 + rr;
        #pragma unroll
        for (int hh = 0; hh < 2; ++hh) {
            const int k4 = hh * 32 + lane;
            const float4 v = *(const float4*)(w_in + (c0 + cc) * 256 + k4 * 4);
            float* d = ws + cc * 257 + k4 * 4;
            d[0] = v.x; d[1] = v.y; d[2] = v.z; d[3] = v.w;
        }
    }
    __syncthreads();

    const int kh = wid >> 2, rg = wid & 3;
    const float* wrow = ws + lane * 257 + kh * 128;
    float acc[2] = {0.f, 0.f};
    #pragma unroll 8
    for (int kq = 0; kq < 32; ++kq) {
        const float w0 = wrow[4 * kq + 0], w1 = wrow[4 * kq + 1];
        const float w2 = wrow[4 * kq + 2], w3 = wrow[4 * kq + 3];
        #pragma unroll
        for (int rr = 0; rr < 2; ++rr) {
            const float4 x4 = *(const float4*)(xs + (rg * 2 + rr) * 256 + kh * 128 + 4 * kq);
            acc[rr] = fmaf(w0, x4.x, fmaf(w1, x4.y, fmaf(w2, x4.z, fmaf(w3, x4.w, acc[rr]))));
        }
    }
    if (kh == 1) {
        #pragma unroll
        for (int rr = 0; rr < 2; ++rr) ps[(rg * 2 + rr) * 32 + lane] = acc[rr];
    }
    __syncthreads();
    if (kh == 0) {
        const float bb = b_in[c0 + lane];
        float* gxs = (float*)g_xs4;
        #pragma unroll
        for (int rr = 0; rr < 2; ++rr) {
            const float val = acc[rr] + ps[(rg * 2 + rr) * 32 + lane] + bb;
            const float mx = wmax(val);
            float p = __expf(val - mx);
            const float smv = wsum(p);
            p = p / smv;

            const int row = r0 + rg * 2 + rr;
            const int b = row >> 7, s = row & 127;
            const int rowo = (b * 8 + hd) * 128 + s;
            gxs[rowo * 32 + lane] = p;

            const float p2o = p * p, p3o = p2o * p;
            float pre1 = 0.f, pre2 = 0.f, pre3 = 0.f;
            int rank = 0;
            #pragma unroll
            for (int f = 0; f < 32; ++f) {
                const float vf = __shfl_sync(0xffffffffu, p, f);
                const bool below = (vf < p) | ((vf == p) & (f < lane));
                if (below) {
                    const float vf2 = vf * vf;
                    pre1 += vf;
                    pre2 += vf2;
                    pre3 += vf2 * vf;
                    ++rank;
                }
            }
            g_sv[rowo * 36 + rank] = p;
            g_qA[rowo * 33 + rank] = 1.f - pre1;
            g_qB[rowo * 33 + rank] = 0.5f * pre2;
            g_qC[rowo * 33 + rank] = -pre3 * (1.f / 6.f);
            if (rank == 31) {
                g_qA[rowo * 33 + 32] = 0.f;
                g_qB[rowo * 33 + 32] = 0.5f * (pre2 + p2o);
                g_qC[rowo * 33 + 32] = -(pre3 + p3o) * (1.f / 6.f);
            }
        }
    }
}

// ---------------------------------------------------------------------------
// K2: spline logits + softmax + AV + partial out-projection.
// grid(128) = ONE wave. Block = (bh, pair): stages tables once, processes
// 16 rows (2 groups of 8 warps). __launch_bounds__(256,1): regs unthrottled.
// ---------------------------------------------------------------------------
__global__ void __launch_bounds__(256, 1) k_spline(const float* __restrict__ w_out,
                                                   float* __restrict__ out) {
    extern __shared__ float sm_raw[];
    float* qA   = sm_raw;                     // [128*33]  (reused as wsm later)
    float* qB   = qA + 128 * 33;
    float* qC   = qB + 128 * 33;
    float* sv   = qC + 128 * 33;              // [128][36]
    float* xsh  = sv + 128 * 36;              // [128][32]
    float* attn = xsh + 128 * 32;             // [8][128] (per row-group, reused)
    float* osm  = attn + 8 * 128;             // [16][32]

    const int t = threadIdx.x, lane = t & 31, wid = t >> 5;
    const int bh = blockIdx.x >> 3, pair = blockIdx.x & 7;
    const int bq = bh >> 3, hq = bh & 7;

    {
        const float4* a = (const float4*)(g_qA + bh * 4224);
        const float4* b = (const float4*)(g_qB + bh * 4224);
        const float4* c = (const float4*)(g_qC + bh * 4224);
        for (int f = t; f < 1056; f += 256) {
            *(float4*)(qA + 4 * f) = a[f];
            *(float4*)(qB + 4 * f) = b[f];
            *(float4*)(qC + 4 * f) = c[f];
        }
        const float4* sp = (const float4*)(g_sv + bh * 4608);
        for (int f = t; f < 1152; f += 256) *(float4*)(sv + 4 * f) = sp[f];
        const float4* xp = g_xs4 + bh * 1024;
        for (int f = t; f < 1024; f += 256) *(float4*)(xsh + 4 * f) = xp[f];
    }
    __syncthreads();

    #pragma unroll
    for (int g = 0; g < 2; ++g) {
        const int il = pair * 16 + g * 8 + wid;      // row index in [0,128)
        const float u  = xsh[il * 32 + lane];
        const float u2 = 0.5f * u * u;
        const float u3 = u * u * u * (1.f / 6.f);

        float srow[4];
        #pragma unroll
        for (int b = 0; b < 4; ++b) {
            float cur[32];
            #pragma unroll
            for (int jj = 0; jj < 32; ++jj) {
                const int j = b * 32 + jj;
                const float* svj = sv + j * 36;
                int r = (svj[15] < u) ? 16 : 0;
                r += (svj[r + 7] < u) ? 8 : 0;
                r += (svj[r + 3] < u) ? 4 : 0;
                r += (svj[r + 1] < u) ? 2 : 0;
                const float2 pr = *(const float2*)(svj + r);
                r += (int)(pr.x < u) + (int)(pr.y < u);
                const int o = j * 33 + r;
                cur[jj] = fmaf(u2, qA[o],
                          fmaf(u,  qB[o],
                          fmaf(u3, __int2float_rn(r), qC[o])));
            }
            #pragma unroll
            for (int o = 16; o > 0; o >>= 1) {
                #pragma unroll
                for (int k = 0; k < o; ++k) {
                    const float keep = (lane & o) ? cur[k + o] : cur[k];
                    const float give = (lane & o) ? cur[k] : cur[k + o];
                    const float got = __shfl_xor_sync(0xffffffffu, give, o);
                    cur[k] = keep + got;
                }
            }
            srow[b] = cur[0];
        }

        const float l0 = srow[0] * (1.f / 32.f), l1 = srow[1] * (1.f / 32.f);
        const float l2 = srow[2] * (1.f / 32.f), l3 = srow[3] * (1.f / 32.f);
        float mx = fmaxf(fmaxf(l0, l1), fmaxf(l2, l3));
        mx = wmax(mx);
        const float e0 = __expf(l0 - mx), e1 = __expf(l1 - mx);
        const float e2 = __expf(l2 - mx), e3 = __expf(l3 - mx);
        float s = (e0 + e1) + (e2 + e3);
        s = wsum(s);
        const float inv = 1.f / s;
        float* at = attn + wid * 128;
        at[0 * 32 + lane] = e0 * inv;
        at[1 * 32 + lane] = e1 * inv;
        at[2 * 32 + lane] = e2 * inv;
        at[3 * 32 + lane] = e3 * inv;
        __syncwarp();

        float a0 = 0.f, a1 = 0.f;
        #pragma unroll 8
        for (int j = 0; j < 128; j += 2) {
            a0 = fmaf(at[j],     xsh[j * 32 + lane],       a0);
            a1 = fmaf(at[j + 1], xsh[(j + 1) * 32 + lane], a1);
        }
        osm[(g * 8 + wid) * 32 + lane] = a0 + a1;
        __syncwarp();
    }
    __syncthreads();   // osm[16][32] ready; spline reads of qA/qB done

    // ---- partial out-projection: out[row, e] += sum_f o[row][f] * w_out[e][hq*32+f]
    float* wsm = qA;   // 256*33 = 8448 floats (fits in qA+qB = 8448)
    for (int g = t; g < 8192; g += 256) {
        const int e = g >> 5, f = g & 31;
        wsm[e * 33 + f] = w_out[(e << 8) + (hq << 5) + f];
    }
    __syncthreads();

    {
        const int e = t;
        float wreg[32];
        #pragma unroll
        for (int f = 0; f < 32; ++f) wreg[f] = wsm[e * 33 + f];

        #pragma unroll
        for (int r = 0; r < 16; ++r) {
            const float4* ob = (const float4*)(osm + r * 32);
            float acc = 0.f;
            #pragma unroll
            for (int k = 0; k < 8; ++k) {
                const float4 o4 = ob[k];
                acc = fmaf(o4.x, wreg[4 * k + 0],
                      fmaf(o4.y, wreg[4 * k + 1],
                      fmaf(o4.z, wreg[4 * k + 2],
                      fmaf(o4.w, wreg[4 * k + 3], acc))));
            }
            const int row = (bq << 7) + pair * 16 + r;
            atomicAdd(out + row * 256 + e, acc);
        }
    }
}

extern "C" void kernel_launch(void* const* d_in, const int* in_sizes, int n_in,
                              void* d_out, int out_size) {
    const float* inp   = (const float*)d_in[0];
    const float* w_in  = (const float*)d_in[1];
    const float* b_in  = (const float*)d_in[2];
    const float* w_out = (const float*)d_in[3];
    const float* b_out = (const float*)d_in[4];
    float* out = (float*)d_out;
    (void)in_sizes; (void)n_in; (void)out_size;

    cudaFuncSetAttribute(k_proj,   cudaFuncAttributeMaxDynamicSharedMemorySize, SMEM_PROJ);
    cudaFuncSetAttribute(k_spline, cudaFuncAttributeMaxDynamicSharedMemorySize, SMEM_SPL);

    k_proj  <<<dim3(32, 8), 256, SMEM_PROJ>>>(inp, w_in, b_in, b_out, out);
    k_spline<<<128, 256, SMEM_SPL>>>(w_out, out);
}

// round 12
// speedup vs baseline: 1.3216x; 1.3216x over previous
#include <cuda_runtime.h>

#define BH_ 16

// gmem scratch
__device__ float4 g_xs4[BH_ * 1024];          // softmaxed x, stride 32 floats
__device__ float  g_sv [BH_ * 128 * 36];      // sorted values, stride 36
__device__ float  g_qA [BH_ * 128 * 33];      // 1 - prefix1(r)     (coeff 0.5u^2)
__device__ float  g_qB [BH_ * 128 * 33];      // 0.5 * prefix2(r)   (coeff u)
__device__ float  g_qC [BH_ * 128 * 33];      // -prefix3(r)/6      (constant)

static const int SMEM_PROJ = (8 * 256 + 32 * 257 + 8 * 32) * 4;            // 42112
static const int SMEM_SPL  = (3 * 128 * 33 + 128 * 36 + 128 * 32
                              + 8 * 128 + 8 * 32) * 4;                     // 90624

__device__ __forceinline__ float wmax(float v) {
    #pragma unroll
    for (int o = 16; o > 0; o >>= 1) v = fmaxf(v, __shfl_xor_sync(0xffffffffu, v, o));
    return v;
}
__device__ __forceinline__ float wsum(float v) {
    #pragma unroll
    for (int o = 16; o > 0; o >>= 1) v += __shfl_xor_sync(0xffffffffu, v, o);
    return v;
}

// ---------------------------------------------------------------------------
// K1: in-proj GEMM + softmax + counting-rank tables + out := b_out (bias init).
// grid(32,8), 256 thr.  [R10]
// ---------------------------------------------------------------------------
__global__ void k_proj(const float* __restrict__ inp,
                       const float* __restrict__ w_in,
                       const float* __restrict__ b_in,
                       const float* __restrict__ b_out,
                       float* __restrict__ out) {
    extern __shared__ float sm[];
    float* xs = sm;                 // [8][256]
    float* ws = sm + 8 * 256;       // [32][257]
    float* ps = ws + 32 * 257;      // [8][32]

    const int t = threadIdx.x, lane = t & 31, wid = t >> 5;
    const int r0 = blockIdx.x * 8, hd = blockIdx.y, c0 = hd * 32;

    {
        const int idx = ((blockIdx.y * 32 + blockIdx.x) << 8) + t;
        out[idx] = b_out[idx & 255];
    }

    #pragma unroll
    for (int f = t; f < 512; f += 256) {
        const int r = f >> 6, kq = f & 63;
        *(float4*)(xs + r * 256 + kq * 4) = *(const float4*)(inp + (r0 + r) * 256 + kq * 4);
    }
    #pragma unroll
    for (int rr = 0; rr < 4; ++rr) {
        const int cc = wid * 4 + rr;
        #pragma unroll
        for (int hh = 0; hh < 2; ++hh) {
            const int k4 = hh * 32 + lane;
            const float4 v = *(const float4*)(w_in + (c0 + cc) * 256 + k4 * 4);
            float* d = ws + cc * 257 + k4 * 4;
            d[0] = v.x; d[1] = v.y; d[2] = v.z; d[3] = v.w;
        }
    }
    __syncthreads();

    const int kh = wid >> 2, rg = wid & 3;
    const float* wrow = ws + lane * 257 + kh * 128;
    float acc[2] = {0.f, 0.f};
    #pragma unroll 8
    for (int kq = 0; kq < 32; ++kq) {
        const float w0 = wrow[4 * kq + 0], w1 = wrow[4 * kq + 1];
        const float w2 = wrow[4 * kq + 2], w3 = wrow[4 * kq + 3];
        #pragma unroll
        for (int rr = 0; rr < 2; ++rr) {
            const float4 x4 = *(const float4*)(xs + (rg * 2 + rr) * 256 + kh * 128 + 4 * kq);
            acc[rr] = fmaf(w0, x4.x, fmaf(w1, x4.y, fmaf(w2, x4.z, fmaf(w3, x4.w, acc[rr]))));
        }
    }
    if (kh == 1) {
        #pragma unroll
        for (int rr = 0; rr < 2; ++rr) ps[(rg * 2 + rr) * 32 + lane] = acc[rr];
    }
    __syncthreads();
    if (kh == 0) {
        const float bb = b_in[c0 + lane];
        float* gxs = (float*)g_xs4;
        #pragma unroll
        for (int rr = 0; rr < 2; ++rr) {
            const float val = acc[rr] + ps[(rg * 2 + rr) * 32 + lane] + bb;
            const float mx = wmax(val);
            float p = __expf(val - mx);
            const float smv = wsum(p);
            p = p / smv;

            const int row = r0 + rg * 2 + rr;
            const int b = row >> 7, s = row & 127;
            const int rowo = (b * 8 + hd) * 128 + s;
            gxs[rowo * 32 + lane] = p;

            const float p2o = p * p, p3o = p2o * p;
            float pre1 = 0.f, pre2 = 0.f, pre3 = 0.f;
            int rank = 0;
            #pragma unroll
            for (int f = 0; f < 32; ++f) {
                const float vf = __shfl_sync(0xffffffffu, p, f);
                const bool below = (vf < p) | ((vf == p) & (f < lane));
                if (below) {
                    const float vf2 = vf * vf;
                    pre1 += vf;
                    pre2 += vf2;
                    pre3 += vf2 * vf;
                    ++rank;
                }
            }
            g_sv[rowo * 36 + rank] = p;
            g_qA[rowo * 33 + rank] = 1.f - pre1;
            g_qB[rowo * 33 + rank] = 0.5f * pre2;
            g_qC[rowo * 33 + rank] = -pre3 * (1.f / 6.f);
            if (rank == 31) {
                g_qA[rowo * 33 + 32] = 0.f;
                g_qB[rowo * 33 + 32] = 0.5f * (pre2 + p2o);
                g_qC[rowo * 33 + 32] = -(pre3 + p3o) * (1.f / 6.f);
            }
        }
    }
}

// ---------------------------------------------------------------------------
// K2: spline logits + row softmax + AV + partial out-projection (atomic add).
// grid(16,16), 256 thr (8 warps). Warp = row i; lane = e.  [R10 + lb(256,2)]
// ---------------------------------------------------------------------------
__global__ void __launch_bounds__(256, 2) k_spline(const float* __restrict__ w_out,
                                                   float* __restrict__ out) {
    extern __shared__ float sm_raw[];
    float* qA   = sm_raw;                     // [128*33]  (reused as wsm later)
    float* qB   = qA + 128 * 33;
    float* qC   = qB + 128 * 33;
    float* sv   = qC + 128 * 33;              // [128][36]
    float* xsh  = sv + 128 * 36;              // [128][32]
    float* attn = xsh + 128 * 32;             // [8][128]
    float* osm  = attn + 8 * 128;             // [8][32]

    const int t = threadIdx.x, lane = t & 31, wid = t >> 5;
    const int bh = blockIdx.y;
    const int bq = bh >> 3, hq = bh & 7;

    {
        const float4* a = (const float4*)(g_qA + bh * 4224);
        const float4* b = (const float4*)(g_qB + bh * 4224);
        const float4* c = (const float4*)(g_qC + bh * 4224);
        for (int f = t; f < 1056; f += 256) {
            *(float4*)(qA + 4 * f) = a[f];
            *(float4*)(qB + 4 * f) = b[f];
            *(float4*)(qC + 4 * f) = c[f];
        }
        const float4* sp = (const float4*)(g_sv + bh * 4608);
        for (int f = t; f < 1152; f += 256) *(float4*)(sv + 4 * f) = sp[f];
        const float4* xp = g_xs4 + bh * 1024;
        for (int f = t; f < 1024; f += 256) *(float4*)(xsh + 4 * f) = xp[f];
    }
    __syncthreads();

    const int i = blockIdx.x * 8 + wid;
    const float u  = xsh[i * 32 + lane];
    const float u2 = 0.5f * u * u;
    const float u3 = u * u * u * (1.f / 6.f);

    float srow[4];
    #pragma unroll
    for (int b = 0; b < 4; ++b) {
        float cur[32];
        #pragma unroll
        for (int jj = 0; jj < 32; ++jj) {
            const int j = b * 32 + jj;
            const float* svj = sv + j * 36;
            int r = (svj[15] < u) ? 16 : 0;
            r += (svj[r + 7] < u) ? 8 : 0;
            r += (svj[r + 3] < u) ? 4 : 0;
            r += (svj[r + 1] < u) ? 2 : 0;
            const float2 pr = *(const float2*)(svj + r);
            r += (int)(pr.x < u) + (int)(pr.y < u);
            const int o = j * 33 + r;
            cur[jj] = fmaf(u2, qA[o],
                      fmaf(u,  qB[o],
                      fmaf(u3, __int2float_rn(r), qC[o])));
        }
        #pragma unroll
        for (int o = 16; o > 0; o >>= 1) {
            #pragma unroll
            for (int k = 0; k < o; ++k) {
                const float keep = (lane & o) ? cur[k + o] : cur[k];
                const float give = (lane & o) ? cur[k] : cur[k + o];
                const float got = __shfl_xor_sync(0xffffffffu, give, o);
                cur[k] = keep + got;
            }
        }
        srow[b] = cur[0];
    }

    const float l0 = srow[0] * (1.f / 32.f), l1 = srow[1] * (1.f / 32.f);
    const float l2 = srow[2] * (1.f / 32.f), l3 = srow[3] * (1.f / 32.f);
    float mx = fmaxf(fmaxf(l0, l1), fmaxf(l2, l3));
    mx = wmax(mx);
    const float e0 = __expf(l0 - mx), e1 = __expf(l1 - mx);
    const float e2 = __expf(l2 - mx), e3 = __expf(l3 - mx);
    float s = (e0 + e1) + (e2 + e3);
    s = wsum(s);
    const float inv = 1.f / s;
    float* at = attn + wid * 128;
    at[0 * 32 + lane] = e0 * inv;
    at[1 * 32 + lane] = e1 * inv;
    at[2 * 32 + lane] = e2 * inv;
    at[3 * 32 + lane] = e3 * inv;
    __syncwarp();

    // o[i, e=lane] = sum_j attn[j] * x[j, e]
    float a0 = 0.f, a1 = 0.f;
    #pragma unroll 8
    for (int j = 0; j < 128; j += 2) {
        a0 = fmaf(at[j],     xsh[j * 32 + lane],       a0);
        a1 = fmaf(at[j + 1], xsh[(j + 1) * 32 + lane], a1);
    }
    osm[wid * 32 + lane] = a0 + a1;
    __syncthreads();

    // ---- partial out-projection: out[row, e] += sum_f o[row][f] * w_out[e][hq*32+f]
    float* wsm = qA;   // 256*33 = 8448 floats
    for (int g = t; g < 8192; g += 256) {
        const int e = g >> 5, f = g & 31;
        wsm[e * 33 + f] = w_out[(e << 8) + (hq << 5) + f];
    }
    __syncthreads();

    {
        const int e = t;
        float wreg[32];
        #pragma unroll
        for (int f = 0; f < 32; ++f) wreg[f] = wsm[e * 33 + f];

        #pragma unroll
        for (int r = 0; r < 8; ++r) {
            const float4* ob = (const float4*)(osm + r * 32);
            float acc = 0.f;
            #pragma unroll
            for (int k = 0; k < 8; ++k) {
                const float4 o4 = ob[k];
                acc = fmaf(o4.x, wreg[4 * k + 0],
                      fmaf(o4.y, wreg[4 * k + 1],
                      fmaf(o4.z, wreg[4 * k + 2],
                      fmaf(o4.w, wreg[4 * k + 3], acc))));
            }
            const int row = (bq << 7) + blockIdx.x * 8 + r;
            atomicAdd(out + row * 256 + e, acc);
        }
    }
}

extern "C" void kernel_launch(void* const* d_in, const int* in_sizes, int n_in,
                              void* d_out, int out_size) {
    const float* inp   = (const float*)d_in[0];
    const float* w_in  = (const float*)d_in[1];
    const float* b_in  = (const float*)d_in[2];
    const float* w_out = (const float*)d_in[3];
    const float* b_out = (const float*)d_in[4];
    float* out = (float*)d_out;
    (void)in_sizes; (void)n_in; (void)out_size;

    cudaFuncSetAttribute(k_proj,   cudaFuncAttributeMaxDynamicSharedMemorySize, SMEM_PROJ);
    cudaFuncSetAttribute(k_spline, cudaFuncAttributeMaxDynamicSharedMemorySize, SMEM_SPL);

    k_proj  <<<dim3(32, 8),  256, SMEM_PROJ>>>(inp, w_in, b_in, b_out, out);
    k_spline<<<dim3(16, 16), 256, SMEM_SPL>>>(w_out, out);
}

// round 13
// speedup vs baseline: 1.3777x; 1.0425x over previous
#include <cuda_runtime.h>

#define BH_ 16

// gmem scratch
__device__ float4 g_xs4[BH_ * 1024];          // softmaxed x, stride 32 floats
__device__ float  g_sv [BH_ * 128 * 36];      // sorted values, stride 36
__device__ float  g_qA [BH_ * 128 * 33];      // 1 - prefix1(r)     (coeff 0.5u^2)
__device__ float  g_qB [BH_ * 128 * 33];      // 0.5 * prefix2(r)   (coeff u)
__device__ float  g_qC [BH_ * 128 * 33];      // -prefix3(r)/6      (constant)

static const int SMEM_PROJ = (8 * 256 + 32 * 257 + 8 * 32) * 4;            // 42112
// floats: qA/qB/qC 3*4224, sv 4608, xsh 4096, attn 1024, osmp 512, osm 256,
//         red 32  -> 23200 floats
static const int SMEM_SPL  = 23200 * 4;                                    // 92800

__device__ __forceinline__ float wmax(float v) {
    #pragma unroll
    for (int o = 16; o > 0; o >>= 1) v = fmaxf(v, __shfl_xor_sync(0xffffffffu, v, o));
    return v;
}
__device__ __forceinline__ float wsum(float v) {
    #pragma unroll
    for (int o = 16; o > 0; o >>= 1) v += __shfl_xor_sync(0xffffffffu, v, o);
    return v;
}

// ---------------------------------------------------------------------------
// K1: in-proj GEMM + softmax + counting-rank tables + out := b_out (bias init).
// grid(32,8), 256 thr.  [unchanged R10]
// ---------------------------------------------------------------------------
__global__ void k_proj(const float* __restrict__ inp,
                       const float* __restrict__ w_in,
                       const float* __restrict__ b_in,
                       const float* __restrict__ b_out,
                       float* __restrict__ out) {
    extern __shared__ float sm[];
    float* xs = sm;                 // [8][256]
    float* ws = sm + 8 * 256;       // [32][257]
    float* ps = ws + 32 * 257;      // [8][32]

    const int t = threadIdx.x, lane = t & 31, wid = t >> 5;
    const int r0 = blockIdx.x * 8, hd = blockIdx.y, c0 = hd * 32;

    {
        const int idx = ((blockIdx.y * 32 + blockIdx.x) << 8) + t;
        out[idx] = b_out[idx & 255];
    }

    #pragma unroll
    for (int f = t; f < 512; f += 256) {
        const int r = f >> 6, kq = f & 63;
        *(float4*)(xs + r * 256 + kq * 4) = *(const float4*)(inp + (r0 + r) * 256 + kq * 4);
    }
    #pragma unroll
    for (int rr = 0; rr < 4; ++rr) {
        const int cc = wid * 4 + rr;
        #pragma unroll
        for (int hh = 0; hh < 2; ++hh) {
            const int k4 = hh * 32 + lane;
            const float4 v = *(const float4*)(w_in + (c0 + cc) * 256 + k4 * 4);
            float* d = ws + cc * 257 + k4 * 4;
            d[0] = v.x; d[1] = v.y; d[2] = v.z; d[3] = v.w;
        }
    }
    __syncthreads();

    const int kh = wid >> 2, rg = wid & 3;
    const float* wrow = ws + lane * 257 + kh * 128;
    float acc[2] = {0.f, 0.f};
    #pragma unroll 8
    for (int kq = 0; kq < 32; ++kq) {
        const float w0 = wrow[4 * kq + 0], w1 = wrow[4 * kq + 1];
        const float w2 = wrow[4 * kq + 2], w3 = wrow[4 * kq + 3];
        #pragma unroll
        for (int rr = 0; rr < 2; ++rr) {
            const float4 x4 = *(const float4*)(xs + (rg * 2 + rr) * 256 + kh * 128 + 4 * kq);
            acc[rr] = fmaf(w0, x4.x, fmaf(w1, x4.y, fmaf(w2, x4.z, fmaf(w3, x4.w, acc[rr]))));
        }
    }
    if (kh == 1) {
        #pragma unroll
        for (int rr = 0; rr < 2; ++rr) ps[(rg * 2 + rr) * 32 + lane] = acc[rr];
    }
    __syncthreads();
    if (kh == 0) {
        const float bb = b_in[c0 + lane];
        float* gxs = (float*)g_xs4;
        #pragma unroll
        for (int rr = 0; rr < 2; ++rr) {
            const float val = acc[rr] + ps[(rg * 2 + rr) * 32 + lane] + bb;
            const float mx = wmax(val);
            float p = __expf(val - mx);
            const float smv = wsum(p);
            p = p / smv;

            const int row = r0 + rg * 2 + rr;
            const int b = row >> 7, s = row & 127;
            const int rowo = (b * 8 + hd) * 128 + s;
            gxs[rowo * 32 + lane] = p;

            const float p2o = p * p, p3o = p2o * p;
            float pre1 = 0.f, pre2 = 0.f, pre3 = 0.f;
            int rank = 0;
            #pragma unroll
            for (int f = 0; f < 32; ++f) {
                const float vf = __shfl_sync(0xffffffffu, p, f);
                const bool below = (vf < p) | ((vf == p) & (f < lane));
                if (below) {
                    const float vf2 = vf * vf;
                    pre1 += vf;
                    pre2 += vf2;
                    pre3 += vf2 * vf;
                    ++rank;
                }
            }
            g_sv[rowo * 36 + rank] = p;
            g_qA[rowo * 33 + rank] = 1.f - pre1;
            g_qB[rowo * 33 + rank] = 0.5f * pre2;
            g_qC[rowo * 33 + rank] = -pre3 * (1.f / 6.f);
            if (rank == 31) {
                g_qA[rowo * 33 + 32] = 0.f;
                g_qB[rowo * 33 + 32] = 0.5f * (pre2 + p2o);
                g_qC[rowo * 33 + 32] = -(pre3 + p3o) * (1.f / 6.f);
            }
        }
    }
}

// ---------------------------------------------------------------------------
// K2: spline + softmax + AV + out-projection. grid(16,16), 512 thr (16 warps).
// Row r owned by warp pair (w, w+8): w does j in [0,64), w+8 does [64,128).
// ---------------------------------------------------------------------------
__global__ void __launch_bounds__(512, 2) k_spline(const float* __restrict__ w_out,
                                                   float* __restrict__ out) {
    extern __shared__ float sm_raw[];
    float* qA   = sm_raw;                     // [128*33]  (reused as wsm later)
    float* qB   = qA + 128 * 33;
    float* qC   = qB + 128 * 33;
    float* sv   = qC + 128 * 33;              // [128][36]
    float* xsh  = sv + 128 * 36;              // [128][32]
    float* attn = xsh + 128 * 32;             // [8][128]
    float* osmp = attn + 8 * 128;             // [2][8][32]
    float* osm  = osmp + 512;                 // [8][32]
    float* redm = osm + 256;                  // [8][2]
    float* reds = redm + 16;                  // [8][2]

    const int t = threadIdx.x, lane = t & 31, wid = t >> 5;
    const int rg = wid & 7, jh = wid >> 3;    // row-group, j-half
    const int bh = blockIdx.y;
    const int bq = bh >> 3, hq = bh & 7;

    {
        const float4* a = (const float4*)(g_qA + bh * 4224);
        const float4* b = (const float4*)(g_qB + bh * 4224);
        const float4* c = (const float4*)(g_qC + bh * 4224);
        for (int f = t; f < 1056; f += 512) {
            *(float4*)(qA + 4 * f) = a[f];
            *(float4*)(qB + 4 * f) = b[f];
            *(float4*)(qC + 4 * f) = c[f];
        }
        const float4* sp = (const float4*)(g_sv + bh * 4608);
        for (int f = t; f < 1152; f += 512) *(float4*)(sv + 4 * f) = sp[f];
        const float4* xp = g_xs4 + bh * 1024;
        for (int f = t; f < 1024; f += 512) *(float4*)(xsh + 4 * f) = xp[f];
    }
    __syncthreads();

    const int i = blockIdx.x * 8 + rg;
    const float u  = xsh[i * 32 + lane];
    const float u2 = 0.5f * u * u;
    const float u3 = u * u * u * (1.f / 6.f);

    float srow[2];
    #pragma unroll
    for (int bb = 0; bb < 2; ++bb) {
        const int b = jh * 2 + bb;
        float cur[32];
        #pragma unroll
        for (int jj = 0; jj < 32; ++jj) {
            const int j = b * 32 + jj;
            const float* svj = sv + j * 36;
            int r = (svj[15] < u) ? 16 : 0;
            r += (svj[r + 7] < u) ? 8 : 0;
            r += (svj[r + 3] < u) ? 4 : 0;
            r += (svj[r + 1] < u) ? 2 : 0;
            const float2 pr = *(const float2*)(svj + r);
            r += (int)(pr.x < u) + (int)(pr.y < u);
            const int o = j * 33 + r;
            cur[jj] = fmaf(u2, qA[o],
                      fmaf(u,  qB[o],
                      fmaf(u3, __int2float_rn(r), qC[o])));
        }
        #pragma unroll
        for (int o = 16; o > 0; o >>= 1) {
            #pragma unroll
            for (int k = 0; k < o; ++k) {
                const float keep = (lane & o) ? cur[k + o] : cur[k];
                const float give = (lane & o) ? cur[k] : cur[k + o];
                const float got = __shfl_xor_sync(0xffffffffu, give, o);
                cur[k] = keep + got;
            }
        }
        srow[bb] = cur[0];
    }

    // cross-warp-pair softmax over 128 logits
    const float l0 = srow[0] * (1.f / 32.f), l1 = srow[1] * (1.f / 32.f);
    float mw = wmax(fmaxf(l0, l1));
    if (lane == 0) redm[rg * 2 + jh] = mw;
    __syncthreads();
    const float mx = fmaxf(redm[rg * 2], redm[rg * 2 + 1]);
    const float e0 = __expf(l0 - mx), e1 = __expf(l1 - mx);
    float sw = wsum(e0 + e1);
    if (lane == 0) reds[rg * 2 + jh] = sw;
    __syncthreads();
    const float inv = 1.f / (reds[rg * 2] + reds[rg * 2 + 1]);
    float* at = attn + rg * 128;
    at[(jh * 2 + 0) * 32 + lane] = e0 * inv;
    at[(jh * 2 + 1) * 32 + lane] = e1 * inv;
    __syncthreads();

    // partial AV over this warp's 64 j's
    {
        const int j0 = jh * 64;
        float a0 = 0.f, a1 = 0.f;
        #pragma unroll 8
        for (int j = j0; j < j0 + 64; j += 2) {
            a0 = fmaf(at[j],     xsh[j * 32 + lane],       a0);
            a1 = fmaf(at[j + 1], xsh[(j + 1) * 32 + lane], a1);
        }
        osmp[(jh * 8 + rg) * 32 + lane] = a0 + a1;
    }
    __syncthreads();

    // combine halves + stage w_out slice (wsm reuses dead qA region)
    if (t < 256) osm[t] = osmp[t] + osmp[256 + t];
    float* wsm = qA;   // 256*33 = 8448 floats
    for (int g = t; g < 8192; g += 512) {
        const int e = g >> 5, f = g & 31;
        wsm[e * 33 + f] = w_out[(e << 8) + (hq << 5) + f];
    }
    __syncthreads();

    // out[row, e] += sum_f osm[row][f] * w_out[e][hq*32+f]; 512 thr = (e, row-half)
    {
        const int e = t & 255, rh = t >> 8;
        float wreg[32];
        #pragma unroll
        for (int f = 0; f < 32; ++f) wreg[f] = wsm[e * 33 + f];

        #pragma unroll
        for (int r = rh * 4; r < rh * 4 + 4; ++r) {
            const float4* ob = (const float4*)(osm + r * 32);
            float acc = 0.f;
            #pragma unroll
            for (int k = 0; k < 8; ++k) {
                const float4 o4 = ob[k];
                acc = fmaf(o4.x, wreg[4 * k + 0],
                      fmaf(o4.y, wreg[4 * k + 1],
                      fmaf(o4.z, wreg[4 * k + 2],
                      fmaf(o4.w, wreg[4 * k + 3], acc))));
            }
            const int row = (bq << 7) + blockIdx.x * 8 + r;
            atomicAdd(out + row * 256 + e, acc);
        }
    }
}

extern "C" void kernel_launch(void* const* d_in, const int* in_sizes, int n_in,
                              void* d_out, int out_size) {
    const float* inp   = (const float*)d_in[0];
    const float* w_in  = (const float*)d_in[1];
    const float* b_in  = (const float*)d_in[2];
    const float* w_out = (const float*)d_in[3];
    const float* b_out = (const float*)d_in[4];
    float* out = (float*)d_out;
    (void)in_sizes; (void)n_in; (void)out_size;

    cudaFuncSetAttribute(k_proj,   cudaFuncAttributeMaxDynamicSharedMemorySize, SMEM_PROJ);
    cudaFuncSetAttribute(k_spline, cudaFuncAttributeMaxDynamicSharedMemorySize, SMEM_SPL);

    k_proj  <<<dim3(32, 8),  256, SMEM_PROJ>>>(inp, w_in, b_in, b_out, out);
    k_spline<<<dim3(16, 16), 512, SMEM_SPL>>>(w_out, out);
}